// round 17
// baseline (speedup 1.0000x reference)
#include <cuda_runtime.h>
#include <math.h>

#define S_LEN 2048
#define DIM   2048
#define NH    32
#define NKV   8
#define HD    64
#define NREP  4           // NH / NKV
#define QSCALE 0.18033688f   // ATT_SCALE * log2(e)
#define LN2    0.69314718f

// ---------------- scratch (device globals; no allocation allowed) ----------
__device__ float g_q[S_LEN * NH * HD];     // 16 MB (dims perm within 8-groups)
__device__ float g_k[S_LEN * NKV * HD];    // 4 MB  (dims perm within 8-groups)
__device__ float g_vt[NKV * HD * S_LEN];   // 4 MB  V^T [head][dim][key], keys perm
__device__ float g_attn[S_LEN * NH * HD];  // 16 MB (tf32-rounded by attn)
__device__ float g_x[S_LEN * DIM];         // 16 MB (tf32-rounded copy of x)

__device__ __forceinline__ unsigned f2tf(float f) {
    unsigned r;
    asm("cvt.rna.tf32.f32 %0, %1;" : "=r"(r) : "f"(f));
    return r;
}
__device__ __forceinline__ float ftf(float f) {
    return __uint_as_float(f2tf(f));
}

__device__ __forceinline__ void cpasync16(void* smem_ptr, const void* gptr) {
    unsigned s = (unsigned)__cvta_generic_to_shared(smem_ptr);
    asm volatile("cp.async.cg.shared.global [%0], [%1], 16;\n" :: "r"(s), "l"(gptr));
}
__device__ __forceinline__ void cp_commit() {
    asm volatile("cp.async.commit_group;\n");
}
__device__ __forceinline__ void cp_wait0() {
    asm volatile("cp.async.wait_group 0;\n");
}
__device__ __forceinline__ void cp_wait1() {
    asm volatile("cp.async.wait_group 1;\n");
}

// ---------------- tf32 round-copy -------------------------------------------
__global__ void round_copy(const float* __restrict__ src, float* __restrict__ dst,
                           int n4)
{
    int i = blockIdx.x * blockDim.x + threadIdx.x;
    if (i >= n4) return;
    float4 v = ((const float4*)src)[i];
    v.x = ftf(v.x); v.y = ftf(v.y); v.z = ftf(v.z); v.w = ftf(v.w);
    ((float4*)dst)[i] = v;
}

// ---------------- TF32 tensor-core GEMM -------------------------------------
// C[M,N] = A[M,K] @ B[N,K]^T + bias[N]; A pre-rounded (pure LDS A-frags).
// 128x128 block tile, BK=32, NSTG=2 cp.async, 8 warps (2x4), warp tile 64x32.
// Epilogue modes: 0 = plain, 1 = fused RoPE + dim-permute (scaled, tf32),
//                 3 = V^T transposed + key-permute (tf32).
#define GSTR  36
#define TILEW (128 * GSTR)
#define ESTR  132

__device__ __forceinline__ void gemm_core(
    const float* __restrict__ A, const float* __restrict__ B,
    const float* __restrict__ bias, float* __restrict__ C,
    int N, int K, int m0, int n0, float* sm, int mode,
    const float* __restrict__ rope_g, float oscale)
{
    float* As = sm;
    float* Bs = sm + 2 * TILEW;

    const int tid  = threadIdx.x;
    const int lane = tid & 31;
    const int w    = tid >> 5;
    const int mw   = (w >> 2) * 64;
    const int nw   = (w & 3) * 32;
    const int g    = lane >> 2;
    const int t    = lane & 3;

    const int lr = tid >> 3;
    const int lc = (tid & 7) << 2;

    float acc[4][4][4];
#pragma unroll
    for (int mt = 0; mt < 4; mt++)
#pragma unroll
        for (int nt = 0; nt < 4; nt++)
#pragma unroll
            for (int r = 0; r < 4; r++) acc[mt][nt][r] = 0.f;

    const int ntiles = K >> 5;

#pragma unroll
    for (int i = 0; i < 4; i++) {
        int r = lr + i * 32;
        cpasync16(&As[r * GSTR + lc], &A[(m0 + r) * K + lc]);
        cpasync16(&Bs[r * GSTR + lc], &B[(n0 + r) * K + lc]);
    }
    cp_commit();
    cp_wait0();
    __syncthreads();

    int st = 0;
    for (int kt = 0; kt < ntiles; kt++) {
        if (kt + 1 < ntiles) {
            const int k0 = (kt + 1) << 5;
            float* an = As + (st ^ 1) * TILEW;
            float* bn = Bs + (st ^ 1) * TILEW;
#pragma unroll
            for (int i = 0; i < 4; i++) {
                int r = lr + i * 32;
                cpasync16(&an[r * GSTR + lc], &A[(m0 + r) * K + k0 + lc]);
                cpasync16(&bn[r * GSTR + lc], &B[(n0 + r) * K + k0 + lc]);
            }
            cp_commit();
        }

        const unsigned* au = (const unsigned*)(As + st * TILEW);
        const float*    bc = Bs + st * TILEW;
#pragma unroll
        for (int ks = 0; ks < 4; ks++) {
            const int kk = ks * 8;
            unsigned bf[4][2];
#pragma unroll
            for (int nt = 0; nt < 4; nt++) {
                bf[nt][0] = f2tf(bc[(nw + nt * 8 + g) * GSTR + kk + t]);
                bf[nt][1] = f2tf(bc[(nw + nt * 8 + g) * GSTR + kk + 4 + t]);
            }
#pragma unroll
            for (int mt = 0; mt < 4; mt++) {
                unsigned a0 = au[(mw + mt * 16 + g) * GSTR + kk + t];
                unsigned a1 = au[(mw + mt * 16 + 8 + g) * GSTR + kk + t];
                unsigned a2 = au[(mw + mt * 16 + g) * GSTR + kk + 4 + t];
                unsigned a3 = au[(mw + mt * 16 + 8 + g) * GSTR + kk + 4 + t];
#pragma unroll
                for (int nt = 0; nt < 4; nt++) {
                    asm volatile(
                        "mma.sync.aligned.m16n8k8.row.col.f32.tf32.tf32.f32 "
                        "{%0,%1,%2,%3}, {%4,%5,%6,%7}, {%8,%9}, {%0,%1,%2,%3};"
                        : "+f"(acc[mt][nt][0]), "+f"(acc[mt][nt][1]),
                          "+f"(acc[mt][nt][2]), "+f"(acc[mt][nt][3])
                        : "r"(a0), "r"(a1), "r"(a2), "r"(a3),
                          "r"(bf[nt][0]), "r"(bf[nt][1]));
                }
            }
        }

        if (kt + 1 < ntiles) cp_wait0();
        __syncthreads();
        st ^= 1;
    }

    if (mode == 1) {
        // ---- fused RoPE + dim-permute epilogue ----
        // stage (acc + bias); then rotate logical dims and write pairs
        // (d, d+4) at physical cols (8*gi + 2j, +1)  [perm j -> 2(j&3)+(j>>2)]
        float* stg = sm;
#pragma unroll
        for (int mt = 0; mt < 4; mt++) {
#pragma unroll
            for (int nt = 0; nt < 4; nt++) {
                int row = mw + mt * 16 + g;
                int col = nw + nt * 8 + t * 2;
                float b0 = bias[n0 + col], b1 = bias[n0 + col + 1];
                stg[row * ESTR + col]           = acc[mt][nt][0] + b0;
                stg[row * ESTR + col + 1]       = acc[mt][nt][1] + b1;
                stg[(row + 8) * ESTR + col]     = acc[mt][nt][2] + b0;
                stg[(row + 8) * ESTR + col + 1] = acc[mt][nt][3] + b1;
            }
        }
        __syncthreads();

        for (int i = tid; i < 128 * 64; i += 256) {
            int row = i >> 6;          // 0..127
            int c   = i & 63;          // pair id (64 pairs over 128 cols)
            int hh  = c >> 5;          // head-half within the 128-col tile
            int p   = c & 31;
            int gi  = p >> 2;          // 8-group 0..7
            int j   = p & 3;
            int d   = gi * 8 + j;      // logical dim; partner d+4
            int s_g = m0 + row;
            float v0 = stg[row * ESTR + hh * 64 + d];
            float v1 = stg[row * ESTR + hh * 64 + d + 4];
            float o0, o1;
            if (d < 32) {
                float cs0 = rope_g[s_g * HD + d];
                float sn0 = rope_g[s_g * HD + 32 + d];
                float cs1 = rope_g[s_g * HD + d + 4];
                float sn1 = rope_g[s_g * HD + 36 + d];
                float x20 = stg[row * ESTR + hh * 64 + d + 32];
                float x21 = stg[row * ESTR + hh * 64 + d + 36];
                o0 = (v0 * cs0 - x20 * sn0) * oscale;
                o1 = (v1 * cs1 - x21 * sn1) * oscale;
            } else {
                int dd = d - 32;
                float cs0 = rope_g[s_g * HD + dd];
                float sn0 = rope_g[s_g * HD + 32 + dd];
                float cs1 = rope_g[s_g * HD + dd + 4];
                float sn1 = rope_g[s_g * HD + 36 + dd];
                float x10 = stg[row * ESTR + hh * 64 + dd];
                float x11 = stg[row * ESTR + hh * 64 + dd + 4];
                o0 = (x10 * sn0 + v0 * cs0) * oscale;
                o1 = (x11 * sn1 + v1 * cs1) * oscale;
            }
            int physc = hh * 64 + gi * 8 + 2 * j;
            *(float2*)&C[s_g * N + n0 + physc] = make_float2(ftf(o0), ftf(o1));
        }
    } else if (mode == 3) {
        // ---- V^T epilogue: C = g_vt [head][dim][key], keys perm in 8-groups
#pragma unroll
        for (int mt = 0; mt < 4; mt++) {
#pragma unroll
            for (int nt = 0; nt < 4; nt++) {
                int colb = n0 + nw + nt * 8 + t * 2;
                int ra = m0 + mw + mt * 16 + g;
                int rb = ra + 8;
                int ka = (ra & ~7) | ((ra & 3) << 1) | ((ra >> 2) & 1);
                int kb = (rb & ~7) | ((rb & 3) << 1) | ((rb >> 2) & 1);
                float b0 = bias[colb], b1 = bias[colb + 1];
#pragma unroll
                for (int rr = 0; rr < 2; rr++) {
                    int col = colb + rr;
                    float bb = rr ? b1 : b0;
                    int base = (col >> 6) * (HD * S_LEN) + (col & 63) * S_LEN;
                    C[base + ka] = ftf(acc[mt][nt][rr] + bb);
                    C[base + kb] = ftf(acc[mt][nt][2 + rr] + bb);
                }
            }
        }
    } else {
#pragma unroll
        for (int mt = 0; mt < 4; mt++) {
#pragma unroll
            for (int nt = 0; nt < 4; nt++) {
                int row = m0 + mw + mt * 16 + g;
                int col = n0 + nw + nt * 8 + t * 2;
                float b0 = bias[col], b1 = bias[col + 1];
                *(float2*)&C[row * N + col] =
                    make_float2(acc[mt][nt][0] + b0, acc[mt][nt][1] + b1);
                *(float2*)&C[(row + 8) * N + col] =
                    make_float2(acc[mt][nt][2] + b0, acc[mt][nt][3] + b1);
            }
        }
    }
}

#define GEMM_SMEM (4 * TILEW * (int)sizeof(float))   // 73728 B

__global__ void __launch_bounds__(256)
qkv_gemm(const float* __restrict__ x, const float* __restrict__ rope_g,
         const float* __restrict__ wq, const float* __restrict__ bq, float* __restrict__ oq,
         const float* __restrict__ wk, const float* __restrict__ bk, float* __restrict__ ok,
         const float* __restrict__ wv, const float* __restrict__ bv, float* __restrict__ ov)
{
    extern __shared__ float sm[];
    const int bx = blockIdx.x;
    const float *B, *bias; float* C; int N, n0, mode; float osc;
    if (bx < 16)      { B = wq; bias = bq; C = oq; N = 2048; n0 = bx * 128;
                        mode = 1; osc = QSCALE; }
    else if (bx < 20) { B = wk; bias = bk; C = ok; N = 512;  n0 = (bx - 16) * 128;
                        mode = 1; osc = 1.0f; }
    else              { B = wv; bias = bv; C = ov; N = 512;  n0 = (bx - 20) * 128;
                        mode = 3; osc = 1.0f; }
    gemm_core(x, B, bias, C, N, DIM, blockIdx.y * 128, n0, sm, mode, rope_g, osc);
}

__global__ void __launch_bounds__(256)
gemm2(const float* __restrict__ A, const float* __restrict__ B,
      const float* __restrict__ bias, float* __restrict__ C, int N, int K)
{
    extern __shared__ float sm[];
    gemm_core(A, B, bias, C, N, K, blockIdx.y * 128, blockIdx.x * 128, sm, 0,
              (const float*)0, 1.0f);
}

// ---------------- Flash attention: LDS.64 fragment pairs --------------------
// BQ=256, BKV=64, 8 warps x 32 q-rows, cp.async double-buffered K/V + Q.
// Contraction dims stored permuted (j -> 2(j&3)+(j>>2) within 8-groups):
// every mma fragment pair is adjacent -> LDS.64. Stride 72 -> bank 8g+2t,
// conflict-free per half-warp. Q pre-scaled by ATT_SCALE*log2(e).
#define QSTR 72
#define KSTR 72
#define VSTR 72
#define PSTR 72
#define ATT_BQ 256
#define ATT_BK 64

#define ATT_SMEM ((ATT_BQ * QSTR + 2 * ATT_BK * KSTR + 2 * ATT_BK * VSTR \
                   + ATT_BQ * PSTR) * (int)sizeof(unsigned))   // 221184 B

__global__ void __launch_bounds__(256)
attn_mma(const float* __restrict__ Q, const float* __restrict__ K,
         const float* __restrict__ VT, const float* __restrict__ sinks,
         float* __restrict__ O)
{
    extern __shared__ unsigned sm_u[];
    unsigned* q_s = sm_u;                           // [256][QSTR]
    float*    k_s = (float*)(q_s + ATT_BQ * QSTR);  // [2][64][KSTR]
    float*    v_s = k_s + 2 * ATT_BK * KSTR;        // [2][64 dims][VSTR keys]
    unsigned* p_s = (unsigned*)(v_s + 2 * ATT_BK * VSTR); // [256][PSTR]

    const int h    = blockIdx.y;
    const int q0   = (gridDim.x - 1 - blockIdx.x) * ATT_BQ;
    const int kvh  = h >> 2;
    const int tid  = threadIdx.x;
    const int lane = tid & 31;
    const int w    = tid >> 5;
    const int g    = lane >> 2;
    const int t    = lane & 3;
    const int mw   = w * 32;
    const int pc0  = 4 * (t & 1) + (t >> 1);  // perm(2t); perm(2t+1)=pc0+2

    const int ntiles = q0 / ATT_BK + 4;
    const float* vbase = VT + kvh * (HD * S_LEN);

    // ---- prologue ----
#pragma unroll
    for (int i = 0; i < 16; i++) {
        int idx = tid + i * 256;
        int row = idx >> 4, c4 = (idx & 15) << 2;
        cpasync16(&q_s[row * QSTR + c4], &Q[(q0 + row) * (NH * HD) + h * HD + c4]);
    }
    cp_commit();
#pragma unroll
    for (int p = 0; p < 2; p++) {
        const int k0 = p * ATT_BK;
        float* kd = k_s + p * ATT_BK * KSTR;
        float* vd = v_s + p * ATT_BK * VSTR;
#pragma unroll
        for (int i = 0; i < 4; i++) {
            int idx = tid + i * 256;
            int row = idx >> 4, c4 = (idx & 15) << 2;
            cpasync16(&kd[row * KSTR + c4], &K[(k0 + row) * (NKV * HD) + kvh * HD + c4]);
            cpasync16(&vd[row * VSTR + c4], &vbase[row * S_LEN + k0 + c4]);
        }
        cp_commit();
    }

    float o[2][8][4];
#pragma unroll
    for (int mt = 0; mt < 2; mt++)
#pragma unroll
        for (int nt = 0; nt < 8; nt++)
#pragma unroll
            for (int r = 0; r < 4; r++) o[mt][nt][r] = 0.f;
    float m_st[2][2], l_st[2][2];
#pragma unroll
    for (int mt = 0; mt < 2; mt++) {
        m_st[mt][0] = -INFINITY; m_st[mt][1] = -INFINITY;
        l_st[mt][0] = 0.f;       l_st[mt][1] = 0.f;
    }

    for (int kt = 0; kt < ntiles; kt++) {
        const int k0 = kt * ATT_BK;
        if (kt + 1 < ntiles) cp_wait1(); else cp_wait0();
        __syncthreads();

        const unsigned* kc = (const unsigned*)(k_s + (kt & 1) * ATT_BK * KSTR);
        const unsigned* vc = (const unsigned*)(v_s + (kt & 1) * ATT_BK * VSTR);

        const bool active = (k0 <= q0 + mw + 31);
        if (active) {
            // ---- S = Q @ K^T (LDS.64 fragment pairs) ----
            float s[2][8][4];
#pragma unroll
            for (int mt = 0; mt < 2; mt++)
#pragma unroll
                for (int nt = 0; nt < 8; nt++)
#pragma unroll
                    for (int r = 0; r < 4; r++) s[mt][nt][r] = 0.f;

#pragma unroll
            for (int ks = 0; ks < 8; ks++) {
                const int kk = ks * 8 + 2 * t;
                uint2 a[2][2];
#pragma unroll
                for (int mt = 0; mt < 2; mt++) {
                    const int rb = (mw + mt * 16 + g) * QSTR;
                    a[mt][0] = *(const uint2*)&q_s[rb + kk];             // a0,a2
                    a[mt][1] = *(const uint2*)&q_s[rb + 8 * QSTR + kk];  // a1,a3
                }
#pragma unroll
                for (int nt = 0; nt < 8; nt++) {
                    uint2 b = *(const uint2*)&kc[(nt * 8 + g) * KSTR + kk];
#pragma unroll
                    for (int mt = 0; mt < 2; mt++) {
                        asm volatile(
                            "mma.sync.aligned.m16n8k8.row.col.f32.tf32.tf32.f32 "
                            "{%0,%1,%2,%3}, {%4,%5,%6,%7}, {%8,%9}, {%0,%1,%2,%3};"
                            : "+f"(s[mt][nt][0]), "+f"(s[mt][nt][1]),
                              "+f"(s[mt][nt][2]), "+f"(s[mt][nt][3])
                            : "r"(a[mt][0].x), "r"(a[mt][1].x),
                              "r"(a[mt][0].y), "r"(a[mt][1].y),
                              "r"(b.x), "r"(b.y));
                    }
                }
            }

            // ---- causal mask (diagonal-region tiles only) ----
            if (k0 + ATT_BK - 1 > q0 + mw) {
#pragma unroll
                for (int mt = 0; mt < 2; mt++) {
                    int qa = q0 + mw + mt * 16 + g;
                    int qb = qa + 8;
#pragma unroll
                    for (int nt = 0; nt < 8; nt++) {
                        int kg0 = k0 + nt * 8 + 2 * t;
                        if (kg0     > qa) s[mt][nt][0] = -1e30f;
                        if (kg0 + 1 > qa) s[mt][nt][1] = -1e30f;
                        if (kg0     > qb) s[mt][nt][2] = -1e30f;
                        if (kg0 + 1 > qb) s[mt][nt][3] = -1e30f;
                    }
                }
            }

            // ---- online softmax (base 2); P stored at permuted key cols ----
#pragma unroll
            for (int mt = 0; mt < 2; mt++) {
                float mlA = -INFINITY, mlB = -INFINITY;
#pragma unroll
                for (int nt = 0; nt < 8; nt++) {
                    mlA = fmaxf(mlA, fmaxf(s[mt][nt][0], s[mt][nt][1]));
                    mlB = fmaxf(mlB, fmaxf(s[mt][nt][2], s[mt][nt][3]));
                }
                mlA = fmaxf(mlA, __shfl_xor_sync(0xffffffffu, mlA, 1));
                mlA = fmaxf(mlA, __shfl_xor_sync(0xffffffffu, mlA, 2));
                mlB = fmaxf(mlB, __shfl_xor_sync(0xffffffffu, mlB, 1));
                mlB = fmaxf(mlB, __shfl_xor_sync(0xffffffffu, mlB, 2));

                float mnA = fmaxf(m_st[mt][0], mlA);
                float mnB = fmaxf(m_st[mt][1], mlB);
                float alA = exp2f(m_st[mt][0] - mnA);
                float alB = exp2f(m_st[mt][1] - mnB);

                float sumA = 0.f, sumB = 0.f;
                const int rbA = (mw + mt * 16 + g) * PSTR;
                const int rbB = rbA + 8 * PSTR;
#pragma unroll
                for (int nt = 0; nt < 8; nt++) {
                    float p0 = exp2f(s[mt][nt][0] - mnA);
                    float p1 = exp2f(s[mt][nt][1] - mnA);
                    float p2 = exp2f(s[mt][nt][2] - mnB);
                    float p3 = exp2f(s[mt][nt][3] - mnB);
                    sumA += p0 + p1;
                    sumB += p2 + p3;
                    int cb = nt * 8 + pc0;
                    p_s[rbA + cb]     = f2tf(p0);
                    p_s[rbA + cb + 2] = f2tf(p1);
                    p_s[rbB + cb]     = f2tf(p2);
                    p_s[rbB + cb + 2] = f2tf(p3);
                }
                sumA += __shfl_xor_sync(0xffffffffu, sumA, 1);
                sumA += __shfl_xor_sync(0xffffffffu, sumA, 2);
                sumB += __shfl_xor_sync(0xffffffffu, sumB, 1);
                sumB += __shfl_xor_sync(0xffffffffu, sumB, 2);

                l_st[mt][0] = l_st[mt][0] * alA + sumA;  m_st[mt][0] = mnA;
                l_st[mt][1] = l_st[mt][1] * alB + sumB;  m_st[mt][1] = mnB;

#pragma unroll
                for (int nt = 0; nt < 8; nt++) {
                    o[mt][nt][0] *= alA; o[mt][nt][1] *= alA;
                    o[mt][nt][2] *= alB; o[mt][nt][3] *= alB;
                }
            }

            __syncwarp();   // p_s rows private to this warp

            // ---- O += P @ V (LDS.64 fragment pairs) ----
#pragma unroll
            for (int ks = 0; ks < 8; ks++) {
                const int kk = ks * 8 + 2 * t;
                uint2 a[2][2];
#pragma unroll
                for (int mt = 0; mt < 2; mt++) {
                    const int rb = (mw + mt * 16 + g) * PSTR;
                    a[mt][0] = *(const uint2*)&p_s[rb + kk];
                    a[mt][1] = *(const uint2*)&p_s[rb + 8 * PSTR + kk];
                }
#pragma unroll
                for (int nt = 0; nt < 8; nt++) {
                    uint2 b = *(const uint2*)&vc[(nt * 8 + g) * VSTR + kk];
#pragma unroll
                    for (int mt = 0; mt < 2; mt++) {
                        asm volatile(
                            "mma.sync.aligned.m16n8k8.row.col.f32.tf32.tf32.f32 "
                            "{%0,%1,%2,%3}, {%4,%5,%6,%7}, {%8,%9}, {%0,%1,%2,%3};"
                            : "+f"(o[mt][nt][0]), "+f"(o[mt][nt][1]),
                              "+f"(o[mt][nt][2]), "+f"(o[mt][nt][3])
                            : "r"(a[mt][0].x), "r"(a[mt][1].x),
                              "r"(a[mt][0].y), "r"(a[mt][1].y),
                              "r"(b.x), "r"(b.y));
                    }
                }
            }
        }
        __syncthreads();

        // issue K/V tile kt+2
        if (kt + 2 < ntiles) {
            const int kn = (kt + 2) * ATT_BK;
            float* kd = k_s + (kt & 1) * ATT_BK * KSTR;
            float* vd = v_s + (kt & 1) * ATT_BK * VSTR;
#pragma unroll
            for (int i = 0; i < 4; i++) {
                int idx = tid + i * 256;
                int row = idx >> 4, c4 = (idx & 15) << 2;
                cpasync16(&kd[row * KSTR + c4], &K[(kn + row) * (NKV * HD) + kvh * HD + c4]);
                cpasync16(&vd[row * VSTR + c4], &vbase[row * S_LEN + kn + c4]);
            }
            cp_commit();
        }
    }

    // ---- epilogue: normalize + sink scale; write tf32-rounded O ----
    float snk = sinks[h];
#pragma unroll
    for (int mt = 0; mt < 2; mt++) {
        int qa = q0 + mw + mt * 16 + g;
        int qb = qa + 8;
        float lseA = (m_st[mt][0] + __log2f(l_st[mt][0])) * LN2;
        float lseB = (m_st[mt][1] + __log2f(l_st[mt][1])) * LN2;
        float invA = (1.f / (1.f + __expf(-(lseA - snk)))) / l_st[mt][0];
        float invB = (1.f / (1.f + __expf(-(lseB - snk)))) / l_st[mt][1];
#pragma unroll
        for (int nt = 0; nt < 8; nt++) {
            int col = nt * 8 + 2 * t;
            *(float2*)&O[qa * (NH * HD) + h * HD + col] =
                make_float2(ftf(o[mt][nt][0] * invA), ftf(o[mt][nt][1] * invA));
            *(float2*)&O[qb * (NH * HD) + h * HD + col] =
                make_float2(ftf(o[mt][nt][2] * invB), ftf(o[mt][nt][3] * invB));
        }
    }
}

// ---------------- launch ----------------------------------------------------
extern "C" void kernel_launch(void* const* d_in, const int* in_sizes, int n_in,
                              void* d_out, int out_size)
{
    const float* x     = (const float*)d_in[0];
    const float* rope  = (const float*)d_in[1];
    const float* wq_w  = (const float*)d_in[2];
    const float* wq_b  = (const float*)d_in[3];
    const float* wk_w  = (const float*)d_in[4];
    const float* wk_b  = (const float*)d_in[5];
    const float* wv_w  = (const float*)d_in[6];
    const float* wv_b  = (const float*)d_in[7];
    const float* wo_w  = (const float*)d_in[8];
    const float* wo_b  = (const float*)d_in[9];
    const float* sinks = (const float*)d_in[10];
    float* out = (float*)d_out;

    float *gq, *gk, *gvt, *ga, *gx;
    cudaGetSymbolAddress((void**)&gq,  g_q);
    cudaGetSymbolAddress((void**)&gk,  g_k);
    cudaGetSymbolAddress((void**)&gvt, g_vt);
    cudaGetSymbolAddress((void**)&ga,  g_attn);
    cudaGetSymbolAddress((void**)&gx,  g_x);

    cudaFuncSetAttribute(qkv_gemm, cudaFuncAttributeMaxDynamicSharedMemorySize,
                         GEMM_SMEM);
    cudaFuncSetAttribute(gemm2, cudaFuncAttributeMaxDynamicSharedMemorySize,
                         GEMM_SMEM);
    cudaFuncSetAttribute(attn_mma, cudaFuncAttributeMaxDynamicSharedMemorySize,
                         ATT_SMEM);

    // tf32 round-copy of x
    const int n4 = (S_LEN * DIM) / 4;
    round_copy<<<(n4 + 255) / 256, 256>>>(x, gx, n4);

    // Fused QKV + RoPE (Q,K dim-permuted; V transposed key-permuted)
    qkv_gemm<<<dim3(24, 16), 256, GEMM_SMEM>>>(gx, rope,
                                               wq_w, wq_b, gq,
                                               wk_w, wk_b, gk,
                                               wv_w, wv_b, gvt);

    // Flash attention (LDS.64 fragments, exp2 softmax, heavy-first)
    attn_mma<<<dim3(S_LEN / ATT_BQ, NH), 256, ATT_SMEM>>>(gq, gk, gvt, sinks, ga);

    // Output projection
    gemm2<<<dim3(16, 16), 256, GEMM_SMEM>>>(ga, wo_w, wo_b, out, DIM, NH * HD);
}